// round 1
// baseline (speedup 1.0000x reference)
#include <cuda_runtime.h>

#define HDIM 64
#define KT 16   // k-tile width (8 f32x2 accumulators)

__device__ __forceinline__ unsigned long long pack2(float lo, float hi) {
    unsigned long long r;
    asm("mov.b64 %0, {%1, %2};" : "=l"(r)
        : "r"(__float_as_uint(lo)), "r"(__float_as_uint(hi)));
    return r;
}

__device__ __forceinline__ void unpack2(unsigned long long v, float& lo, float& hi) {
    unsigned int a, b;
    asm("mov.b64 {%0, %1}, %2;" : "=r"(a), "=r"(b) : "l"(v));
    lo = __uint_as_float(a);
    hi = __uint_as_float(b);
}

// Packed fp32x2 FMA: 2 FMAs per instruction (Blackwell double-rate fp32 path,
// only reachable from PTX fma.rn.f32x2).
__device__ __forceinline__ unsigned long long fma2(unsigned long long a,
                                                   unsigned long long b,
                                                   unsigned long long c) {
    unsigned long long d;
    asm("fma.rn.f32x2 %0, %1, %2, %3;" : "=l"(d) : "l"(a), "l"(b), "l"(c));
    return d;
}

// One CTA = one feature f x 128 batch rows. W2[f] staged in smem (16 KB),
// each thread owns one batch row: h1 (duplicated into f32x2 halves) lives in
// registers, the 64x64 hidden matmul runs as packed f32x2 FMAs over k-pairs.
__global__ void __launch_bounds__(128, 1) nam_main(
    const float* __restrict__ x,   // (B, F)
    const float* __restrict__ W1,  // (F, H)
    const float* __restrict__ b1,  // (F, H)
    const float* __restrict__ W2,  // (F, H, H)
    const float* __restrict__ b2,  // (F, H)
    const float* __restrict__ W3,  // (F, H)
    const float* __restrict__ b3,  // (F,)
    float* __restrict__ fnn,       // (B, F)
    int B, int F)
{
    __shared__ __align__(16) float sW2[HDIM * HDIM];
    __shared__ float sW1[HDIM], sb1[HDIM], sb2[HDIM], sW3[HDIM];
    __shared__ float sb3v;

    const int f = blockIdx.x;
    const float* W2f = W2 + (size_t)f * HDIM * HDIM;
    for (int i = threadIdx.x; i < HDIM * HDIM; i += 128)
        sW2[i] = W2f[i];
    if (threadIdx.x < HDIM) {
        sW1[threadIdx.x] = W1[f * HDIM + threadIdx.x];
        sb1[threadIdx.x] = b1[f * HDIM + threadIdx.x];
        sb2[threadIdx.x] = b2[f * HDIM + threadIdx.x];
        sW3[threadIdx.x] = W3[f * HDIM + threadIdx.x];
    }
    if (threadIdx.x == 0) sb3v = b3[f];
    __syncthreads();

    const int b = blockIdx.y * 128 + threadIdx.x;
    const float xv = x[(size_t)b * F + f];

    // Layer 1: h1[h] = relu(x * W1 + b1), duplicated into both f32x2 halves.
    unsigned long long h1d[HDIM];
    #pragma unroll
    for (int h = 0; h < HDIM; ++h) {
        float v = fmaxf(fmaf(xv, sW1[h], sb1[h]), 0.0f);
        h1d[h] = pack2(v, v);
    }

    float out = sb3v;

    // Layer 2 + 3: for each k-tile, acc[k,k+1] pairs accumulate over h with
    // packed FMAs; the W2 pair load is a natural LDS.64 broadcast.
    for (int kt = 0; kt < HDIM; kt += KT) {
        unsigned long long acc[KT / 2];
        #pragma unroll
        for (int j = 0; j < KT / 2; ++j)
            acc[j] = pack2(sb2[kt + 2 * j], sb2[kt + 2 * j + 1]);

        #pragma unroll
        for (int h = 0; h < HDIM; ++h) {
            const unsigned long long* wrow =
                reinterpret_cast<const unsigned long long*>(sW2 + h * HDIM + kt);
            #pragma unroll
            for (int j = 0; j < KT / 2; ++j)
                acc[j] = fma2(h1d[h], wrow[j], acc[j]);
        }

        #pragma unroll
        for (int j = 0; j < KT / 2; ++j) {
            float lo, hi;
            unpack2(acc[j], lo, hi);
            lo = fmaxf(lo, 0.0f);
            hi = fmaxf(hi, 0.0f);
            out = fmaf(lo, sW3[kt + 2 * j], out);
            out = fmaf(hi, sW3[kt + 2 * j + 1], out);
        }
    }

    fnn[(size_t)b * F + f] = out;
}

// out[b] = sum_f fnn[b, f]  (deterministic warp-per-row reduction, coalesced)
__global__ void nam_reduce(const float* __restrict__ fnn,
                           float* __restrict__ out, int B, int F)
{
    int warp = (blockIdx.x * blockDim.x + threadIdx.x) >> 5;
    int lane = threadIdx.x & 31;
    if (warp >= B) return;
    const float* row = fnn + (size_t)warp * F;
    float s = 0.0f;
    for (int j = lane; j < F; j += 32) s += row[j];
    #pragma unroll
    for (int o = 16; o; o >>= 1) s += __shfl_down_sync(0xFFFFFFFFu, s, o);
    if (lane == 0) out[warp] = s;
}

extern "C" void kernel_launch(void* const* d_in, const int* in_sizes, int n_in,
                              void* d_out, int out_size)
{
    const float* x  = (const float*)d_in[0];
    const float* W1 = (const float*)d_in[1];
    const float* b1 = (const float*)d_in[2];
    const float* W2 = (const float*)d_in[3];
    const float* b2 = (const float*)d_in[4];
    const float* W3 = (const float*)d_in[5];
    const float* b3 = (const float*)d_in[6];

    const int F = in_sizes[6];            // (F,) bias
    const int B = in_sizes[0] / F;        // inputs is (B, F)

    float* out = (float*)d_out;           // (B,)
    float* fnn = out + B;                 // (B, F)

    dim3 grid(F, B / 128);
    nam_main<<<grid, 128>>>(x, W1, b1, W2, b2, W3, b3, fnn, B, F);

    const int rows_per_block = 8;         // 256 threads = 8 warps = 8 rows
    int blocks = (B + rows_per_block - 1) / rows_per_block;
    nam_reduce<<<blocks, 256>>>(fnn, out, B, F);
}

// round 3
// speedup vs baseline: 1.3831x; 1.3831x over previous
#include <cuda_runtime.h>

#define HDIM 64
#define ROWS_PER_CTA 256
#define THREADS 128

typedef unsigned long long ull;

__device__ __forceinline__ ull pack2(float lo, float hi) {
    ull r;
    asm("mov.b64 %0, {%1, %2};" : "=l"(r)
        : "r"(__float_as_uint(lo)), "r"(__float_as_uint(hi)));
    return r;
}

__device__ __forceinline__ void unpack2(ull v, float& lo, float& hi) {
    unsigned int a, b;
    asm("mov.b64 {%0, %1}, %2;" : "=r"(a), "=r"(b) : "l"(v));
    lo = __uint_as_float(a);
    hi = __uint_as_float(b);
}

// Packed fp32x2 FMA (Blackwell double-rate fp32, PTX-only).
__device__ __forceinline__ ull fma2(ull a, ull b, ull c) {
    ull d;
    asm("fma.rn.f32x2 %0, %1, %2, %3;" : "=l"(d) : "l"(a), "l"(b), "l"(c));
    return d;
}

// One CTA = (feature f) x (256 batch rows). Register-tiled GEMM:
// each thread computes a 16-row x 8-col microtile of h2 = relu(h1 @ W2 + b2)
// as f32x2 row-pairs. sA = h1 transposed [h][row]; sW2d = W2 with each
// scalar duplicated so LDS.128 yields ready f32x2 multiplicands.
__global__ void __launch_bounds__(THREADS, 2) nam_main(
    const float* __restrict__ x,
    const float* __restrict__ W1,
    const float* __restrict__ b1,
    const float* __restrict__ W2,
    const float* __restrict__ b2,
    const float* __restrict__ W3,
    const float* __restrict__ b3,
    float* __restrict__ fnn,
    int B, int F)
{
    extern __shared__ float smem[];
    float* sA   = smem;                        // [64][256]
    float* sW2d = smem + HDIM * ROWS_PER_CTA;  // [64][128]

    __shared__ float sw1[HDIM], sb1[HDIM], sb2[HDIM], sw3[HDIM];
    __shared__ float sb3v;

    const int f   = blockIdx.x;
    const int tid = threadIdx.x;
    const int rg  = tid >> 3;
    const int kg  = tid & 7;

    if (tid < HDIM) {
        sw1[tid] = W1[f * HDIM + tid];
        sb1[tid] = b1[f * HDIM + tid];
        sb2[tid] = b2[f * HDIM + tid];
        sw3[tid] = W3[f * HDIM + tid];
    }
    if (tid == 0) sb3v = b3[f];
    __syncthreads();

    const float* W2f = W2 + (size_t)f * HDIM * HDIM;
    #pragma unroll
    for (int i = tid; i < HDIM * HDIM; i += THREADS) {
        float w = W2f[i];
        int h = i >> 6, k = i & 63;
        *reinterpret_cast<ull*>(sW2d + h * 2 * HDIM + 2 * k) = pack2(w, w);
    }

    const int brow0 = blockIdx.y * ROWS_PER_CTA + 2 * tid;
    const float x0 = x[(size_t)brow0 * F + f];
    const float x1 = x[(size_t)(brow0 + 1) * F + f];
    #pragma unroll
    for (int h = 0; h < HDIM; ++h) {
        float w = sw1[h], bb = sb1[h];
        float v0 = fmaxf(fmaf(x0, w, bb), 0.0f);
        float v1 = fmaxf(fmaf(x1, w, bb), 0.0f);
        *reinterpret_cast<ull*>(sA + h * ROWS_PER_CTA + 2 * tid) = pack2(v0, v1);
    }
    __syncthreads();

    ull acc[8][8];
    #pragma unroll
    for (int k = 0; k < 8; ++k) {
        float bv = sb2[kg * 8 + k];
        ull d = pack2(bv, bv);
        #pragma unroll
        for (int p = 0; p < 8; ++p) acc[p][k] = d;
    }

    const float* aBase = sA + rg * 16;
    const float* wBase = sW2d + kg * 16;

    #pragma unroll 4
    for (int h = 0; h < HDIM; ++h) {
        const ulonglong2* ap = reinterpret_cast<const ulonglong2*>(aBase + h * ROWS_PER_CTA);
        const ulonglong2* wp = reinterpret_cast<const ulonglong2*>(wBase + h * 2 * HDIM);
        ull aa[8], ww[8];
        #pragma unroll
        for (int q = 0; q < 4; ++q) {
            ulonglong2 av = ap[q];
            aa[2 * q] = av.x; aa[2 * q + 1] = av.y;
            ulonglong2 wv = wp[q];
            ww[2 * q] = wv.x; ww[2 * q + 1] = wv.y;
        }
        #pragma unroll
        for (int p = 0; p < 8; ++p)
            #pragma unroll
            for (int k = 0; k < 8; ++k)
                acc[p][k] = fma2(aa[p], ww[k], acc[p][k]);
    }

    float s0[8], s1[8];
    #pragma unroll
    for (int p = 0; p < 8; ++p) { s0[p] = 0.0f; s1[p] = 0.0f; }
    #pragma unroll
    for (int k = 0; k < 8; ++k) {
        float w3k = sw3[kg * 8 + k];
        #pragma unroll
        for (int p = 0; p < 8; ++p) {
            float e0, e1;
            unpack2(acc[p][k], e0, e1);
            s0[p] = fmaf(fmaxf(e0, 0.0f), w3k, s0[p]);
            s1[p] = fmaf(fmaxf(e1, 0.0f), w3k, s1[p]);
        }
    }

    __syncthreads();
    float* sRed = sW2d;  // [8][256]
    #pragma unroll
    for (int p = 0; p < 8; ++p) {
        int row = rg * 16 + 2 * p;
        *reinterpret_cast<ull*>(sRed + kg * ROWS_PER_CTA + row) = pack2(s0[p], s1[p]);
    }
    __syncthreads();

    #pragma unroll
    for (int j = 0; j < 2; ++j) {
        int r = tid + j * THREADS;
        float v = sb3v;
        #pragma unroll
        for (int g = 0; g < 8; ++g) v += sRed[g * ROWS_PER_CTA + r];
        fnn[(size_t)(blockIdx.y * ROWS_PER_CTA + r) * F + f] = v;
    }
}

__global__ void nam_reduce(const float* __restrict__ fnn,
                           float* __restrict__ out, int B, int F)
{
    int warp = (blockIdx.x * blockDim.x + threadIdx.x) >> 5;
    int lane = threadIdx.x & 31;
    if (warp >= B) return;
    const float4* row = reinterpret_cast<const float4*>(fnn + (size_t)warp * F);
    int n4 = F >> 2;
    float s = 0.0f;
    for (int j = lane; j < n4; j += 32) {
        float4 v = row[j];
        s += (v.x + v.y) + (v.z + v.w);
    }
    #pragma unroll
    for (int o = 16; o; o >>= 1) s += __shfl_down_sync(0xFFFFFFFFu, s, o);
    if (lane == 0) out[warp] = s;
}

extern "C" void kernel_launch(void* const* d_in, const int* in_sizes, int n_in,
                              void* d_out, int out_size)
{
    const float* x  = (const float*)d_in[0];
    const float* W1 = (const float*)d_in[1];
    const float* b1 = (const float*)d_in[2];
    const float* W2 = (const float*)d_in[3];
    const float* b2 = (const float*)d_in[4];
    const float* W3 = (const float*)d_in[5];
    const float* b3 = (const float*)d_in[6];

    const int F = in_sizes[6];
    const int B = in_sizes[0] / F;

    float* out = (float*)d_out;
    float* fnn = out + B;

    const int smemBytes = (HDIM * ROWS_PER_CTA + HDIM * 2 * HDIM) * sizeof(float);
    cudaFuncSetAttribute(nam_main, cudaFuncAttributeMaxDynamicSharedMemorySize, smemBytes);

    dim3 grid(F, B / ROWS_PER_CTA);
    nam_main<<<grid, THREADS, smemBytes>>>(x, W1, b1, W2, b2, W3, b3, fnn, B, F);

    const int rows_per_block = 8;
    int blocks = (B + rows_per_block - 1) / rows_per_block;
    nam_reduce<<<blocks, 256>>>(fnn, out, B, F);
}

// round 6
// speedup vs baseline: 3.3755x; 2.4406x over previous
#include <cuda_runtime.h>
#include <cstdint>

#define HDIM    64
#define MTILE   128
#define THREADS 128
#define PW      72          // row pitch in 32-bit words (bank-conflict-free)

typedef unsigned long long ull;

// A tiles: [128 rows][72 words], B tiles: [64 n][72 words]; word layout per
// row: w[2j] = bf16pair(hi[2j],hi[2j+1]), w[2j+1] = bf16pair(lo...), so one
// LDS.64 returns both splits of a k-pair.
#define SA_WORDS (MTILE * PW)
#define SB_WORDS (HDIM * PW)
#define SMEM_BYTES ((SA_WORDS + SB_WORDS) * 4)

__device__ __forceinline__ uint16_t bf16b(float v) {
    uint16_t r;
    asm("cvt.rn.bf16.f32 %0, %1;" : "=h"(r) : "f"(v));
    return r;
}

__device__ __forceinline__ void split2(float v0, float v1,
                                       uint32_t& hiw, uint32_t& low) {
    uint16_t h0 = bf16b(v0), h1 = bf16b(v1);
    float r0 = v0 - __uint_as_float((uint32_t)h0 << 16);
    float r1 = v1 - __uint_as_float((uint32_t)h1 << 16);
    uint16_t l0 = bf16b(r0), l1 = bf16b(r1);
    hiw = (uint32_t)h0 | ((uint32_t)h1 << 16);
    low = (uint32_t)l0 | ((uint32_t)l1 << 16);
}

__device__ __forceinline__ void mma16816(float* d, uint32_t a0, uint32_t a1,
                                         uint32_t a2, uint32_t a3,
                                         uint32_t b0, uint32_t b1) {
    asm volatile(
        "mma.sync.aligned.m16n8k16.row.col.f32.bf16.bf16.f32 "
        "{%0,%1,%2,%3}, {%4,%5,%6,%7}, {%8,%9}, {%0,%1,%2,%3};"
        : "+f"(d[0]), "+f"(d[1]), "+f"(d[2]), "+f"(d[3])
        : "r"(a0), "r"(a1), "r"(a2), "r"(a3), "r"(b0), "r"(b1));
}

// One CTA = (feature f) x (128 batch rows). Layer1 -> split-bf16 A tile,
// W2^T -> split-bf16 B tile, layer2 via mma.sync (3-product bf16 split),
// fused epilogue bias+relu+W3-dot straight from accumulator fragments.
__global__ void __launch_bounds__(THREADS, 2) nam_mma(
    const float* __restrict__ x,
    const float* __restrict__ W1,
    const float* __restrict__ b1,
    const float* __restrict__ W2,
    const float* __restrict__ b2,
    const float* __restrict__ W3,
    const float* __restrict__ b3,
    float* __restrict__ fnn,
    int B, int F)
{
    extern __shared__ __align__(16) uint32_t smw[];
    uint32_t* sAw = smw;             // [128][72]
    uint32_t* sBw = smw + SA_WORDS;  // [64][72]

    __shared__ float sw1[HDIM], sb1[HDIM], sb2[HDIM], sw3[HDIM];
    __shared__ float sb3v;

    const int f    = blockIdx.x;
    const int tid  = threadIdx.x;
    const int wid  = tid >> 5;
    const int lane = tid & 31;
    const int g    = lane >> 2;      // row/col group 0..7
    const int tig  = lane & 3;       // thread in group

    if (tid < HDIM) {
        sw1[tid] = W1[f * HDIM + tid];
        sb1[tid] = b1[f * HDIM + tid];
        sb2[tid] = b2[f * HDIM + tid];
        sw3[tid] = W3[f * HDIM + tid];
    }
    if (tid == 0) sb3v = b3[f];
    __syncthreads();

    // ---- B tile: W2 transposed ([n][h]) with hi/lo interleaved pairs ----
    const float* W2f = W2 + (size_t)f * HDIM * HDIM;
    #pragma unroll
    for (int it = 0; it < 16; ++it) {
        int p  = tid + it * THREADS;       // 0..2047
        int k  = p & 63;                   // n index
        int hp = p >> 6;                   // h pair 0..31
        float v0 = W2f[(2 * hp) * HDIM + k];
        float v1 = W2f[(2 * hp + 1) * HDIM + k];
        uint32_t hw, lw;
        split2(v0, v1, hw, lw);
        ull* dst = reinterpret_cast<ull*>(sBw + k * PW + 2 * hp);
        *dst = (ull)hw | ((ull)lw << 32);
    }

    // ---- A tile: layer 1, one batch row per thread ----
    const int brow = blockIdx.y * MTILE + tid;
    const float xv = x[(size_t)brow * F + f];
    #pragma unroll
    for (int j = 0; j < 32; ++j) {
        float v0 = fmaxf(fmaf(xv, sw1[2 * j], sb1[2 * j]), 0.0f);
        float v1 = fmaxf(fmaf(xv, sw1[2 * j + 1], sb1[2 * j + 1]), 0.0f);
        uint32_t hw, lw;
        split2(v0, v1, hw, lw);
        ull* dst = reinterpret_cast<ull*>(sAw + tid * PW + 2 * j);
        *dst = (ull)hw | ((ull)lw << 32);
    }
    __syncthreads();

    // ---- main loop: warp owns 32 rows (2 m16 tiles) x 64 cols ----
    float d[2][8][4];
    #pragma unroll
    for (int mt = 0; mt < 2; ++mt)
        #pragma unroll
        for (int nt = 0; nt < 8; ++nt)
            #pragma unroll
            for (int q = 0; q < 4; ++q) d[mt][nt][q] = 0.0f;

    const int rowBase = wid * 32;
    const int woff    = 2 * tig;

    #pragma unroll
    for (int ks = 0; ks < 4; ++ks) {
        const int kw = ks * 16 + woff;
        uint32_t ah[2][4], al[2][4];
        #pragma unroll
        for (int mt = 0; mt < 2; ++mt) {
            int r0 = rowBase + mt * 16 + g;
            ull A0 = *reinterpret_cast<const ull*>(sAw + r0 * PW + kw);
            ull A1 = *reinterpret_cast<const ull*>(sAw + (r0 + 8) * PW + kw);
            ull A2 = *reinterpret_cast<const ull*>(sAw + r0 * PW + kw + 8);
            ull A3 = *reinterpret_cast<const ull*>(sAw + (r0 + 8) * PW + kw + 8);
            ah[mt][0] = (uint32_t)A0; al[mt][0] = (uint32_t)(A0 >> 32);
            ah[mt][1] = (uint32_t)A1; al[mt][1] = (uint32_t)(A1 >> 32);
            ah[mt][2] = (uint32_t)A2; al[mt][2] = (uint32_t)(A2 >> 32);
            ah[mt][3] = (uint32_t)A3; al[mt][3] = (uint32_t)(A3 >> 32);
        }
        #pragma unroll
        for (int nt = 0; nt < 8; ++nt) {
            int n = nt * 8 + g;
            ull B0 = *reinterpret_cast<const ull*>(sBw + n * PW + kw);
            ull B1 = *reinterpret_cast<const ull*>(sBw + n * PW + kw + 8);
            uint32_t bh0 = (uint32_t)B0, bl0 = (uint32_t)(B0 >> 32);
            uint32_t bh1 = (uint32_t)B1, bl1 = (uint32_t)(B1 >> 32);
            #pragma unroll
            for (int mt = 0; mt < 2; ++mt) {
                mma16816(d[mt][nt], ah[mt][0], ah[mt][1], ah[mt][2], ah[mt][3], bh0, bh1);
                mma16816(d[mt][nt], ah[mt][0], ah[mt][1], ah[mt][2], ah[mt][3], bl0, bl1);
                mma16816(d[mt][nt], al[mt][0], al[mt][1], al[mt][2], al[mt][3], bh0, bh1);
            }
        }
    }

    // ---- epilogue: bias + relu + W3 dot, reduce over tig, write fnn ----
    #pragma unroll
    for (int mt = 0; mt < 2; ++mt) {
        float s0 = 0.0f, s1 = 0.0f;   // rows g, g+8
        #pragma unroll
        for (int nt = 0; nt < 8; ++nt) {
            int n0 = nt * 8 + 2 * tig;
            float bb0 = sb2[n0],     w30 = sw3[n0];
            float bb1 = sb2[n0 + 1], w31 = sw3[n0 + 1];
            s0 = fmaf(fmaxf(d[mt][nt][0] + bb0, 0.0f), w30, s0);
            s0 = fmaf(fmaxf(d[mt][nt][1] + bb1, 0.0f), w31, s0);
            s1 = fmaf(fmaxf(d[mt][nt][2] + bb0, 0.0f), w30, s1);
            s1 = fmaf(fmaxf(d[mt][nt][3] + bb1, 0.0f), w31, s1);
        }
        s0 += __shfl_xor_sync(0xFFFFFFFFu, s0, 1);
        s0 += __shfl_xor_sync(0xFFFFFFFFu, s0, 2);
        s1 += __shfl_xor_sync(0xFFFFFFFFu, s1, 1);
        s1 += __shfl_xor_sync(0xFFFFFFFFu, s1, 2);
        if (tig == 0) {
            int row = blockIdx.y * MTILE + rowBase + mt * 16 + g;
            fnn[(size_t)row * F + f]       = s0 + sb3v;
            fnn[(size_t)(row + 8) * F + f] = s1 + sb3v;
        }
    }
}

// out[b] = sum_f fnn[b, f]
__global__ void nam_reduce(const float* __restrict__ fnn,
                           float* __restrict__ out, int B, int F)
{
    int warp = (blockIdx.x * blockDim.x + threadIdx.x) >> 5;
    int lane = threadIdx.x & 31;
    if (warp >= B) return;
    const float4* row = reinterpret_cast<const float4*>(fnn + (size_t)warp * F);
    int n4 = F >> 2;
    float s = 0.0f;
    for (int j = lane; j < n4; j += 32) {
        float4 v = row[j];
        s += (v.x + v.y) + (v.z + v.w);
    }
    #pragma unroll
    for (int o = 16; o; o >>= 1) s += __shfl_down_sync(0xFFFFFFFFu, s, o);
    if (lane == 0) out[warp] = s;
}

extern "C" void kernel_launch(void* const* d_in, const int* in_sizes, int n_in,
                              void* d_out, int out_size)
{
    const float* x  = (const float*)d_in[0];
    const float* W1 = (const float*)d_in[1];
    const float* b1 = (const float*)d_in[2];
    const float* W2 = (const float*)d_in[3];
    const float* b2 = (const float*)d_in[4];
    const float* W3 = (const float*)d_in[5];
    const float* b3 = (const float*)d_in[6];

    const int F = in_sizes[6];
    const int B = in_sizes[0] / F;

    float* out = (float*)d_out;   // (B,)
    float* fnn = out + B;         // (B, F)

    cudaFuncSetAttribute(nam_mma, cudaFuncAttributeMaxDynamicSharedMemorySize,
                         SMEM_BYTES);

    dim3 grid(F, B / MTILE);
    nam_mma<<<grid, THREADS, SMEM_BYTES>>>(x, W1, b1, W2, b2, W3, b3, fnn, B, F);

    const int rows_per_block = 8;
    int blocks = (B + rows_per_block - 1) / rows_per_block;
    nam_reduce<<<blocks, 256>>>(fnn, out, B, F);
}

// round 7
// speedup vs baseline: 5.9789x; 1.7712x over previous
#include <cuda_runtime.h>
#include <cuda_fp16.h>
#include <cstdint>

#define HDIM    64
#define MTILE   128
#define THREADS 128
#define PWA     36     // A row pitch in words (conflict-free fragment loads)
#define PWB     72     // B row pitch in words (hi/lo interleaved pairs)
#define FMAX    128

typedef unsigned long long ull;

#define SA_WORDS (MTILE * PWA)          // 4608 words = 18 KB
#define SB_WORDS (HDIM * PWB)           // 4608 words = 18 KB
#define SMEM_BYTES ((SA_WORDS + SB_WORDS) * 4)

// Precomputed fp16 hi/lo split of W2^T, stored as the exact smem image
// ([n][PWB] words) per feature.
__device__ uint4 g_w2s[FMAX * (SB_WORDS / 4)];

__device__ __forceinline__ void mma_f16(float* d, uint32_t a0, uint32_t a1,
                                        uint32_t a2, uint32_t a3,
                                        uint32_t b0, uint32_t b1) {
    asm volatile(
        "mma.sync.aligned.m16n8k16.row.col.f32.f16.f16.f32 "
        "{%0,%1,%2,%3}, {%4,%5,%6,%7}, {%8,%9}, {%0,%1,%2,%3};"
        : "+f"(d[0]), "+f"(d[1]), "+f"(d[2]), "+f"(d[3])
        : "r"(a0), "r"(a1), "r"(a2), "r"(a3), "r"(b0), "r"(b1));
}

// ---- prep: split W2[f]^T into fp16 hi/lo interleaved image, once per f ----
__global__ void nam_prep(const float* __restrict__ W2, int F)
{
    const int f   = blockIdx.x;
    const int tid = threadIdx.x;
    const float* W2f = W2 + (size_t)f * HDIM * HDIM;
    uint32_t* img = reinterpret_cast<uint32_t*>(g_w2s) + (size_t)f * SB_WORDS;

    #pragma unroll
    for (int it = 0; it < 16; ++it) {
        int p  = tid + it * THREADS;    // 0..2047
        int n  = p & 63;
        int hp = p >> 6;                // h-pair 0..31
        float v0 = W2f[(2 * hp) * HDIM + n];
        float v1 = W2f[(2 * hp + 1) * HDIM + n];
        __half h0 = __float2half_rn(v0), h1 = __float2half_rn(v1);
        __half l0 = __float2half_rn(v0 - __half2float(h0));
        __half l1 = __float2half_rn(v1 - __half2float(h1));
        uint32_t hiw = (uint32_t)__half_as_ushort(h0) |
                       ((uint32_t)__half_as_ushort(h1) << 16);
        uint32_t low = (uint32_t)__half_as_ushort(l0) |
                       ((uint32_t)__half_as_ushort(l1) << 16);
        img[n * PWB + 2 * hp]     = hiw;
        img[n * PWB + 2 * hp + 1] = low;
    }
    // zero the pad words so the copy is deterministic
    #pragma unroll
    for (int n = tid >> 3; n < HDIM; n += THREADS / 8)
        img[n * PWB + 64 + (tid & 7)] = 0;
}

// One CTA = (feature f) x (128 batch rows). A = fp16(h1) (no split);
// B = fp16 hi/lo split of W2^T; layer2 = 2 MMAs per tile (Ah@Bh + Ah@Bl).
__global__ void __launch_bounds__(THREADS, 3) nam_mma(
    const float* __restrict__ x,
    const float* __restrict__ W1,
    const float* __restrict__ b1,
    const float* __restrict__ b2,
    const float* __restrict__ W3,
    const float* __restrict__ b3,
    float* __restrict__ fnn,
    int B, int F)
{
    extern __shared__ __align__(16) uint32_t smw[];
    uint32_t* sAw = smw;             // [128][36]
    uint32_t* sBw = smw + SA_WORDS;  // [64][72]

    __shared__ float sw1[HDIM], sb1[HDIM], sb2[HDIM], sw3[HDIM];
    __shared__ float sb3v;

    const int f    = blockIdx.x;
    const int tid  = threadIdx.x;
    const int wid  = tid >> 5;
    const int lane = tid & 31;
    const int g    = lane >> 2;
    const int tig  = lane & 3;

    if (tid < HDIM) {
        sw1[tid] = W1[f * HDIM + tid];
        sb1[tid] = b1[f * HDIM + tid];
        sb2[tid] = b2[f * HDIM + tid];
        sw3[tid] = W3[f * HDIM + tid];
    }
    if (tid == 0) sb3v = b3[f];

    // ---- B tile: plain vector copy of the precomputed split image ----
    {
        const uint4* src = g_w2s + (size_t)f * (SB_WORDS / 4);
        uint4* dst = reinterpret_cast<uint4*>(sBw);
        #pragma unroll
        for (int i = 0; i < SB_WORDS / 4 / THREADS; ++i)
            dst[tid + i * THREADS] = src[tid + i * THREADS];
    }
    __syncthreads();   // sw1/sb1 ready

    // ---- A tile: layer 1, one batch row per thread, plain fp16 ----
    const int brow = blockIdx.y * MTILE + tid;
    const float xv = x[(size_t)brow * F + f];
    #pragma unroll
    for (int j = 0; j < 32; ++j) {
        float v0 = fmaxf(fmaf(xv, sw1[2 * j], sb1[2 * j]), 0.0f);
        float v1 = fmaxf(fmaf(xv, sw1[2 * j + 1], sb1[2 * j + 1]), 0.0f);
        __half2 h2v = __floats2half2_rn(v0, v1);
        sAw[tid * PWA + j] = *reinterpret_cast<uint32_t*>(&h2v);
    }
    __syncthreads();

    // ---- main loop: warp owns 32 rows (2 m16 tiles) x 64 cols ----
    float d[2][8][4];
    #pragma unroll
    for (int mt = 0; mt < 2; ++mt)
        #pragma unroll
        for (int nt = 0; nt < 8; ++nt)
            #pragma unroll
            for (int q = 0; q < 4; ++q) d[mt][nt][q] = 0.0f;

    const int rowBase = wid * 32;

    #pragma unroll
    for (int ks = 0; ks < 4; ++ks) {
        uint32_t a[2][4];
        #pragma unroll
        for (int mt = 0; mt < 2; ++mt) {
            int r0 = rowBase + mt * 16 + g;
            int w0 = ks * 8 + tig;
            a[mt][0] = sAw[r0 * PWA + w0];
            a[mt][1] = sAw[(r0 + 8) * PWA + w0];
            a[mt][2] = sAw[r0 * PWA + w0 + 4];
            a[mt][3] = sAw[(r0 + 8) * PWA + w0 + 4];
        }
        #pragma unroll
        for (int nt = 0; nt < 8; ++nt) {
            int n = nt * 8 + g;
            ull B0 = *reinterpret_cast<const ull*>(sBw + n * PWB + 2 * (ks * 8 + tig));
            ull B1 = *reinterpret_cast<const ull*>(sBw + n * PWB + 2 * (ks * 8 + 4 + tig));
            uint32_t bh0 = (uint32_t)B0, bl0 = (uint32_t)(B0 >> 32);
            uint32_t bh1 = (uint32_t)B1, bl1 = (uint32_t)(B1 >> 32);
            #pragma unroll
            for (int mt = 0; mt < 2; ++mt) {
                mma_f16(d[mt][nt], a[mt][0], a[mt][1], a[mt][2], a[mt][3], bh0, bh1);
                mma_f16(d[mt][nt], a[mt][0], a[mt][1], a[mt][2], a[mt][3], bl0, bl1);
            }
        }
    }

    // ---- epilogue: bias + relu + W3 dot, reduce over tig, write fnn ----
    #pragma unroll
    for (int mt = 0; mt < 2; ++mt) {
        float s0 = 0.0f, s1 = 0.0f;   // rows g, g+8
        #pragma unroll
        for (int nt = 0; nt < 8; ++nt) {
            int n0 = nt * 8 + 2 * tig;
            float bb0 = sb2[n0],     w30 = sw3[n0];
            float bb1 = sb2[n0 + 1], w31 = sw3[n0 + 1];
            s0 = fmaf(fmaxf(d[mt][nt][0] + bb0, 0.0f), w30, s0);
            s0 = fmaf(fmaxf(d[mt][nt][1] + bb1, 0.0f), w31, s0);
            s1 = fmaf(fmaxf(d[mt][nt][2] + bb0, 0.0f), w30, s1);
            s1 = fmaf(fmaxf(d[mt][nt][3] + bb1, 0.0f), w31, s1);
        }
        s0 += __shfl_xor_sync(0xFFFFFFFFu, s0, 1);
        s0 += __shfl_xor_sync(0xFFFFFFFFu, s0, 2);
        s1 += __shfl_xor_sync(0xFFFFFFFFu, s1, 1);
        s1 += __shfl_xor_sync(0xFFFFFFFFu, s1, 2);
        if (tig == 0) {
            int row = blockIdx.y * MTILE + rowBase + mt * 16 + g;
            fnn[(size_t)row * F + f]       = s0 + sb3v;
            fnn[(size_t)(row + 8) * F + f] = s1 + sb3v;
        }
    }
}

// out[b] = sum_f fnn[b, f]
__global__ void nam_reduce(const float* __restrict__ fnn,
                           float* __restrict__ out, int B, int F)
{
    int warp = (blockIdx.x * blockDim.x + threadIdx.x) >> 5;
    int lane = threadIdx.x & 31;
    if (warp >= B) return;
    const float4* row = reinterpret_cast<const float4*>(fnn + (size_t)warp * F);
    int n4 = F >> 2;
    float s = 0.0f;
    for (int j = lane; j < n4; j += 32) {
        float4 v = row[j];
        s += (v.x + v.y) + (v.z + v.w);
    }
    #pragma unroll
    for (int o = 16; o; o >>= 1) s += __shfl_down_sync(0xFFFFFFFFu, s, o);
    if (lane == 0) out[warp] = s;
}

extern "C" void kernel_launch(void* const* d_in, const int* in_sizes, int n_in,
                              void* d_out, int out_size)
{
    const float* x  = (const float*)d_in[0];
    const float* W1 = (const float*)d_in[1];
    const float* b1 = (const float*)d_in[2];
    const float* W2 = (const float*)d_in[3];
    const float* b2 = (const float*)d_in[4];
    const float* W3 = (const float*)d_in[5];
    const float* b3 = (const float*)d_in[6];

    const int F = in_sizes[6];
    const int B = in_sizes[0] / F;

    float* out = (float*)d_out;   // (B,)
    float* fnn = out + B;         // (B, F)

    cudaFuncSetAttribute(nam_mma, cudaFuncAttributeMaxDynamicSharedMemorySize,
                         SMEM_BYTES);

    nam_prep<<<F, THREADS>>>(W2, F);

    dim3 grid(F, B / MTILE);
    nam_mma<<<grid, THREADS, SMEM_BYTES>>>(x, W1, b1, b2, W3, b3, fnn, B, F);

    const int rows_per_block = 8;
    int blocks = (B + rows_per_block - 1) / rows_per_block;
    nam_reduce<<<blocks, 256>>>(fnn, out, B, F);
}

// round 8
// speedup vs baseline: 7.7522x; 1.2966x over previous
#include <cuda_runtime.h>
#include <cuda_fp16.h>
#include <cstdint>

#define HDIM    64
#define MTILE   128
#define THREADS 128
#define PWA     36     // A row pitch in words (bank-conflict-free)
#define PWB     36     // B row pitch in words
#define FMAX    128

typedef unsigned long long ull;

#define SA_WORDS (MTILE * PWA)          // 4608 words = 18 KB
#define SB_WORDS (HDIM * PWB)           // 2304 words = 9 KB
#define SMEM_BYTES ((SA_WORDS + SB_WORDS) * 4)

// Precomputed fp16 image of W2^T ([n][PWB] words) per feature.
__device__ uint4 g_w2s[FMAX * (SB_WORDS / 4)];

__device__ __forceinline__ void mma_f16(float* d, uint32_t a0, uint32_t a1,
                                        uint32_t a2, uint32_t a3,
                                        uint32_t b0, uint32_t b1) {
    asm volatile(
        "mma.sync.aligned.m16n8k16.row.col.f32.f16.f16.f32 "
        "{%0,%1,%2,%3}, {%4,%5,%6,%7}, {%8,%9}, {%0,%1,%2,%3};"
        : "+f"(d[0]), "+f"(d[1]), "+f"(d[2]), "+f"(d[3])
        : "r"(a0), "r"(a1), "r"(a2), "r"(a3), "r"(b0), "r"(b1));
}

// ---- prep: W2[f]^T -> fp16 pair image, once per feature ----
__global__ void nam_prep(const float* __restrict__ W2, int F)
{
    const int f   = blockIdx.x;
    const int tid = threadIdx.x;                 // 256 threads
    const float* W2f = W2 + (size_t)f * HDIM * HDIM;
    uint32_t* img = reinterpret_cast<uint32_t*>(g_w2s) + (size_t)f * SB_WORDS;

    #pragma unroll
    for (int it = 0; it < 8; ++it) {
        int p  = tid + it * 256;                 // 0..2047
        int n  = p & 63;
        int hp = p >> 6;                         // h-pair 0..31
        float v0 = W2f[(2 * hp) * HDIM + n];
        float v1 = W2f[(2 * hp + 1) * HDIM + n];
        __half2 h2 = __floats2half2_rn(v0, v1);
        img[n * PWB + hp] = *reinterpret_cast<uint32_t*>(&h2);
    }
    // zero pad words (deterministic copy source)
    {
        int n = tid >> 2, j = tid & 3;
        img[n * PWB + 32 + j] = 0;
    }
}

// One CTA = (feature f) x (128 batch rows). A = fp16(h1), B = fp16(W2^T),
// layer2 = single-product m16n8k16 HMMA; fused bias+relu+W3 epilogue.
__global__ void __launch_bounds__(THREADS, 4) nam_mma(
    const float* __restrict__ x,
    const float* __restrict__ W1,
    const float* __restrict__ b1,
    const float* __restrict__ b2,
    const float* __restrict__ W3,
    const float* __restrict__ b3,
    float* __restrict__ fnn,
    int B, int F)
{
    extern __shared__ __align__(16) uint32_t smw[];
    uint32_t* sAw = smw;             // [128][36]
    uint32_t* sBw = smw + SA_WORDS;  // [64][36]

    __shared__ float sw1[HDIM], sb1[HDIM], sb2[HDIM], sw3[HDIM];
    __shared__ float sb3v;

    const int f    = blockIdx.x;
    const int tid  = threadIdx.x;
    const int wid  = tid >> 5;
    const int lane = tid & 31;
    const int g    = lane >> 2;
    const int tig  = lane & 3;

    if (tid < HDIM) {
        sw1[tid] = W1[f * HDIM + tid];
        sb1[tid] = b1[f * HDIM + tid];
        sb2[tid] = b2[f * HDIM + tid];
        sw3[tid] = W3[f * HDIM + tid];
    }
    if (tid == 0) sb3v = b3[f];

    // ---- B tile: vector copy of precomputed fp16 image (576 uint4) ----
    {
        const uint4* src = g_w2s + (size_t)f * (SB_WORDS / 4);
        uint4* dst = reinterpret_cast<uint4*>(sBw);
        #pragma unroll
        for (int i = tid; i < SB_WORDS / 4; i += THREADS)
            dst[i] = src[i];
    }
    __syncthreads();   // sw1/sb1 ready

    // ---- A tile: layer 1, one batch row per thread ----
    const int brow = blockIdx.y * MTILE + tid;
    const float xv = x[(size_t)brow * F + f];
    #pragma unroll
    for (int j = 0; j < 32; ++j) {
        float v0 = fmaxf(fmaf(xv, sw1[2 * j], sb1[2 * j]), 0.0f);
        float v1 = fmaxf(fmaf(xv, sw1[2 * j + 1], sb1[2 * j + 1]), 0.0f);
        __half2 h2v = __floats2half2_rn(v0, v1);
        sAw[tid * PWA + j] = *reinterpret_cast<uint32_t*>(&h2v);
    }
    __syncthreads();

    // ---- main loop: warp owns 32 rows (2 m16 tiles) x 64 cols ----
    float d[2][8][4];
    #pragma unroll
    for (int mt = 0; mt < 2; ++mt)
        #pragma unroll
        for (int nt = 0; nt < 8; ++nt)
            #pragma unroll
            for (int q = 0; q < 4; ++q) d[mt][nt][q] = 0.0f;

    const int rowBase = wid * 32;

    #pragma unroll
    for (int ks = 0; ks < 4; ++ks) {
        const int w0 = ks * 8 + tig;
        uint32_t a[2][4];
        #pragma unroll
        for (int mt = 0; mt < 2; ++mt) {
            int r0 = rowBase + mt * 16 + g;
            a[mt][0] = sAw[r0 * PWA + w0];
            a[mt][1] = sAw[(r0 + 8) * PWA + w0];
            a[mt][2] = sAw[r0 * PWA + w0 + 4];
            a[mt][3] = sAw[(r0 + 8) * PWA + w0 + 4];
        }
        #pragma unroll
        for (int nt = 0; nt < 8; ++nt) {
            int n = nt * 8 + g;
            uint32_t b0 = sBw[n * PWB + w0];
            uint32_t b1 = sBw[n * PWB + w0 + 4];
            #pragma unroll
            for (int mt = 0; mt < 2; ++mt)
                mma_f16(d[mt][nt], a[mt][0], a[mt][1], a[mt][2], a[mt][3], b0, b1);
        }
    }

    // ---- epilogue: bias + relu + W3 dot, reduce over tig, write fnn ----
    #pragma unroll
    for (int mt = 0; mt < 2; ++mt) {
        float s0 = 0.0f, s1 = 0.0f;   // rows g, g+8
        #pragma unroll
        for (int nt = 0; nt < 8; ++nt) {
            int n0 = nt * 8 + 2 * tig;
            float bb0 = sb2[n0],     w30 = sw3[n0];
            float bb1 = sb2[n0 + 1], w31 = sw3[n0 + 1];
            s0 = fmaf(fmaxf(d[mt][nt][0] + bb0, 0.0f), w30, s0);
            s0 = fmaf(fmaxf(d[mt][nt][1] + bb1, 0.0f), w31, s0);
            s1 = fmaf(fmaxf(d[mt][nt][2] + bb0, 0.0f), w30, s1);
            s1 = fmaf(fmaxf(d[mt][nt][3] + bb1, 0.0f), w31, s1);
        }
        s0 += __shfl_xor_sync(0xFFFFFFFFu, s0, 1);
        s0 += __shfl_xor_sync(0xFFFFFFFFu, s0, 2);
        s1 += __shfl_xor_sync(0xFFFFFFFFu, s1, 1);
        s1 += __shfl_xor_sync(0xFFFFFFFFu, s1, 2);
        if (tig == 0) {
            int row = blockIdx.y * MTILE + rowBase + mt * 16 + g;
            fnn[(size_t)row * F + f]       = s0 + sb3v;
            fnn[(size_t)(row + 8) * F + f] = s1 + sb3v;
        }
    }
}

// out[b] = sum_f fnn[b, f]
__global__ void nam_reduce(const float* __restrict__ fnn,
                           float* __restrict__ out, int B, int F)
{
    int warp = (blockIdx.x * blockDim.x + threadIdx.x) >> 5;
    int lane = threadIdx.x & 31;
    if (warp >= B) return;
    const float4* row = reinterpret_cast<const float4*>(fnn + (size_t)warp * F);
    int n4 = F >> 2;
    float s = 0.0f;
    for (int j = lane; j < n4; j += 32) {
        float4 v = row[j];
        s += (v.x + v.y) + (v.z + v.w);
    }
    #pragma unroll
    for (int o = 16; o; o >>= 1) s += __shfl_down_sync(0xFFFFFFFFu, s, o);
    if (lane == 0) out[warp] = s;
}

extern "C" void kernel_launch(void* const* d_in, const int* in_sizes, int n_in,
                              void* d_out, int out_size)
{
    const float* x  = (const float*)d_in[0];
    const float* W1 = (const float*)d_in[1];
    const float* b1 = (const float*)d_in[2];
    const float* W2 = (const float*)d_in[3];
    const float* b2 = (const float*)d_in[4];
    const float* W3 = (const float*)d_in[5];
    const float* b3 = (const float*)d_in[6];

    const int F = in_sizes[6];
    const int B = in_sizes[0] / F;

    float* out = (float*)d_out;   // (B,)
    float* fnn = out + B;         // (B, F)

    cudaFuncSetAttribute(nam_mma, cudaFuncAttributeMaxDynamicSharedMemorySize,
                         SMEM_BYTES);

    nam_prep<<<F, 256>>>(W2, F);

    dim3 grid(F, B / MTILE);
    nam_mma<<<grid, THREADS, SMEM_BYTES>>>(x, W1, b1, b2, W3, b3, fnn, B, F);

    const int rows_per_block = 8;
    int blocks = (B + rows_per_block - 1) / rows_per_block;
    nam_reduce<<<blocks, 256>>>(fnn, out, B, F);
}

// round 9
// speedup vs baseline: 8.3489x; 1.0770x over previous
#include <cuda_runtime.h>
#include <cuda_fp16.h>
#include <cstdint>

#define HDIM    64
#define MTILE   128
#define THREADS 128
#define PWA     36
#define PWB     36
#define FMAX    128
#define BMAX    8192

typedef unsigned long long ull;

#define SA_WORDS (MTILE * PWA)          // 4608 words = 18 KB
#define SB_WORDS (HDIM * PWB)           // 2304 words = 9 KB
#define SMEM_BYTES ((SA_WORDS + SB_WORDS) * 4)

__device__ uint4 g_w2s[FMAX * (SB_WORDS / 4)];  // fp16 W2^T smem image per f
__device__ float g_xT[FMAX * BMAX];             // x transposed (F, B)
__device__ float g_fnnT[FMAX * BMAX];           // fnn transposed (F, B)

__device__ __forceinline__ void mma_f16(float* d, uint32_t a0, uint32_t a1,
                                        uint32_t a2, uint32_t a3,
                                        uint32_t b0, uint32_t b1) {
    asm volatile(
        "mma.sync.aligned.m16n8k16.row.col.f32.f16.f16.f32 "
        "{%0,%1,%2,%3}, {%4,%5,%6,%7}, {%8,%9}, {%0,%1,%2,%3};"
        : "+f"(d[0]), "+f"(d[1]), "+f"(d[2]), "+f"(d[3])
        : "r"(a0), "r"(a1), "r"(a2), "r"(a3), "r"(b0), "r"(b1));
}

// ---- prep: (blocks < F) W2[f]^T fp16 image; (rest) 32x32 transpose of x ----
__global__ void nam_prep(const float* __restrict__ W2,
                         const float* __restrict__ x, int B, int F)
{
    const int bid = blockIdx.x;
    const int tid = threadIdx.x;                  // 256 threads

    if (bid < F) {
        const float* W2f = W2 + (size_t)bid * HDIM * HDIM;
        uint32_t* img = reinterpret_cast<uint32_t*>(g_w2s) + (size_t)bid * SB_WORDS;
        #pragma unroll
        for (int it = 0; it < 8; ++it) {
            int p  = tid + it * 256;              // 0..2047
            int n  = p & 63;
            int hp = p >> 6;
            float v0 = W2f[(2 * hp) * HDIM + n];
            float v1 = W2f[(2 * hp + 1) * HDIM + n];
            __half2 h2 = __floats2half2_rn(v0, v1);
            img[n * PWB + hp] = *reinterpret_cast<uint32_t*>(&h2);
        }
        { int n = tid >> 2, j = tid & 3; img[n * PWB + 32 + j] = 0; }
    } else {
        __shared__ float tile[32][33];
        const int t  = bid - F;
        const int NB = B >> 5;
        const int fb = t / NB, bt = t % NB;
        const int tx = tid & 31, ty = tid >> 5;   // ty 0..7
        #pragma unroll
        for (int i = 0; i < 4; ++i) {
            int b = bt * 32 + ty + i * 8;
            tile[ty + i * 8][tx] = x[(size_t)b * F + fb * 32 + tx];
        }
        __syncthreads();
        #pragma unroll
        for (int i = 0; i < 4; ++i) {
            int f = fb * 32 + ty + i * 8;
            g_xT[(size_t)f * B + bt * 32 + tx] = tile[tx][ty + i * 8];
        }
    }
}

// One CTA = (feature f) x (128 batch rows). A = fp16(h1), B = fp16(W2^T),
// single-product m16n8k16 HMMA; fused bias+relu+W3 epilogue -> fnnT.
__global__ void __launch_bounds__(THREADS, 4) nam_mma(
    const float* __restrict__ W1,
    const float* __restrict__ b1,
    const float* __restrict__ b2,
    const float* __restrict__ W3,
    const float* __restrict__ b3,
    int B, int F)
{
    extern __shared__ __align__(16) uint32_t smw[];
    uint32_t* sAw = smw;             // [128][36]
    uint32_t* sBw = smw + SA_WORDS;  // [64][36]

    __shared__ float sw1[HDIM], sb1[HDIM], sb2[HDIM], sw3[HDIM];
    __shared__ float sb3v;

    const int f    = blockIdx.x;
    const int tid  = threadIdx.x;
    const int wid  = tid >> 5;
    const int lane = tid & 31;
    const int g    = lane >> 2;
    const int tig  = lane & 3;

    if (tid < HDIM) {
        sw1[tid] = W1[f * HDIM + tid];
        sb1[tid] = b1[f * HDIM + tid];
        sb2[tid] = b2[f * HDIM + tid];
        sw3[tid] = W3[f * HDIM + tid];
    }
    if (tid == 0) sb3v = b3[f];

    // ---- B tile: vector copy of precomputed fp16 image ----
    {
        const uint4* src = g_w2s + (size_t)f * (SB_WORDS / 4);
        uint4* dst = reinterpret_cast<uint4*>(sBw);
        #pragma unroll
        for (int i = tid; i < SB_WORDS / 4; i += THREADS)
            dst[i] = src[i];
    }
    __syncthreads();

    // ---- A tile: layer 1, one batch row per thread (coalesced xT read) ----
    const float xv = g_xT[(size_t)f * B + blockIdx.y * MTILE + tid];
    #pragma unroll
    for (int jq = 0; jq < 8; ++jq) {
        uint32_t w[4];
        #pragma unroll
        for (int jj = 0; jj < 4; ++jj) {
            int j = jq * 4 + jj;
            float v0 = fmaxf(fmaf(xv, sw1[2 * j], sb1[2 * j]), 0.0f);
            float v1 = fmaxf(fmaf(xv, sw1[2 * j + 1], sb1[2 * j + 1]), 0.0f);
            __half2 h2v = __floats2half2_rn(v0, v1);
            w[jj] = *reinterpret_cast<uint32_t*>(&h2v);
        }
        *reinterpret_cast<uint4*>(sAw + tid * PWA + jq * 4) =
            make_uint4(w[0], w[1], w[2], w[3]);
    }
    __syncthreads();

    // ---- main loop: warp owns 32 rows (2 m16 tiles) x 64 cols ----
    float d[2][8][4];
    #pragma unroll
    for (int mt = 0; mt < 2; ++mt)
        #pragma unroll
        for (int nt = 0; nt < 8; ++nt)
            #pragma unroll
            for (int q = 0; q < 4; ++q) d[mt][nt][q] = 0.0f;

    const int rowBase = wid * 32;

    #pragma unroll
    for (int ks = 0; ks < 4; ++ks) {
        const int w0 = ks * 8 + tig;
        uint32_t a[2][4];
        #pragma unroll
        for (int mt = 0; mt < 2; ++mt) {
            int r0 = rowBase + mt * 16 + g;
            a[mt][0] = sAw[r0 * PWA + w0];
            a[mt][1] = sAw[(r0 + 8) * PWA + w0];
            a[mt][2] = sAw[r0 * PWA + w0 + 4];
            a[mt][3] = sAw[(r0 + 8) * PWA + w0 + 4];
        }
        #pragma unroll
        for (int nt = 0; nt < 8; ++nt) {
            int n = nt * 8 + g;
            uint32_t b0 = sBw[n * PWB + w0];
            uint32_t b1 = sBw[n * PWB + w0 + 4];
            #pragma unroll
            for (int mt = 0; mt < 2; ++mt)
                mma_f16(d[mt][nt], a[mt][0], a[mt][1], a[mt][2], a[mt][3], b0, b1);
        }
    }

    // ---- epilogue: bias + relu + W3 dot -> smem stage -> coalesced fnnT ----
    __syncthreads();                 // done reading sAw
    float* sFn = reinterpret_cast<float*>(sAw);
    #pragma unroll
    for (int mt = 0; mt < 2; ++mt) {
        float s0 = 0.0f, s1 = 0.0f;
        #pragma unroll
        for (int nt = 0; nt < 8; ++nt) {
            int n0 = nt * 8 + 2 * tig;
            float bb0 = sb2[n0],     w30 = sw3[n0];
            float bb1 = sb2[n0 + 1], w31 = sw3[n0 + 1];
            s0 = fmaf(fmaxf(d[mt][nt][0] + bb0, 0.0f), w30, s0);
            s0 = fmaf(fmaxf(d[mt][nt][1] + bb1, 0.0f), w31, s0);
            s1 = fmaf(fmaxf(d[mt][nt][2] + bb0, 0.0f), w30, s1);
            s1 = fmaf(fmaxf(d[mt][nt][3] + bb1, 0.0f), w31, s1);
        }
        s0 += __shfl_xor_sync(0xFFFFFFFFu, s0, 1);
        s0 += __shfl_xor_sync(0xFFFFFFFFu, s0, 2);
        s1 += __shfl_xor_sync(0xFFFFFFFFu, s1, 1);
        s1 += __shfl_xor_sync(0xFFFFFFFFu, s1, 2);
        if (tig == 0) {
            int r = rowBase + mt * 16 + g;
            sFn[r]     = s0 + sb3v;
            sFn[r + 8] = s1 + sb3v;
        }
    }
    __syncthreads();
    g_fnnT[(size_t)f * B + blockIdx.y * MTILE + tid] = sFn[tid];
}

// finish: per 32-batch tile, out[b] = sum_f fnnT[f][b]; transpose to fnn (B,F).
__global__ void nam_finish(float* __restrict__ out, float* __restrict__ fnn,
                           int B, int F)
{
    __shared__ float tile[FMAX][33];
    __shared__ float ps[8][32];

    const int b0 = blockIdx.x * 32;
    const int t  = threadIdx.x;        // 256
    const int bl = t & 31, fc = t >> 5;  // fc 0..7

    float s = 0.0f;
    #pragma unroll
    for (int i = 0; i < 16; ++i) {
        int f = fc * 16 + i;
        float v = g_fnnT[(size_t)f * B + b0 + bl];
        s += v;
        tile[f][bl] = v;
    }
    ps[fc][bl] = s;
    __syncthreads();

    if (t < 32) {
        float o = 0.0f;
        #pragma unroll
        for (int i = 0; i < 8; ++i) o += ps[i][t];
        out[b0 + t] = o;
    }

    const int col = t & 127, rr = t >> 7;   // 2 rows per iteration
    #pragma unroll
    for (int r = 0; r < 32; r += 2)
        fnn[(size_t)(b0 + r + rr) * F + col] = tile[col][r + rr];
}

extern "C" void kernel_launch(void* const* d_in, const int* in_sizes, int n_in,
                              void* d_out, int out_size)
{
    const float* x  = (const float*)d_in[0];
    const float* W1 = (const float*)d_in[1];
    const float* b1 = (const float*)d_in[2];
    const float* W2 = (const float*)d_in[3];
    const float* b2 = (const float*)d_in[4];
    const float* W3 = (const float*)d_in[5];
    const float* b3 = (const float*)d_in[6];

    const int F = in_sizes[6];
    const int B = in_sizes[0] / F;

    float* out = (float*)d_out;   // (B,)
    float* fnn = out + B;         // (B, F)

    cudaFuncSetAttribute(nam_mma, cudaFuncAttributeMaxDynamicSharedMemorySize,
                         SMEM_BYTES);

    const int tBlocks = (F / 32) * (B / 32);
    nam_prep<<<F + tBlocks, 256>>>(W2, x, B, F);

    dim3 grid(F, B / MTILE);
    nam_mma<<<grid, THREADS, SMEM_BYTES>>>(W1, b1, b2, W3, b3, B, F);

    nam_finish<<<B / 32, 256>>>(out, fnn, B, F);
}